// round 3
// baseline (speedup 1.0000x reference)
#include <cuda_runtime.h>
#include <cstdint>

#define SLEN 4096
#define NB   32
#define HD   512

// scratch (static device arrays — no allocation)
__device__ float g_whb[HD * NB];        // whb[k][n] transposed: (hidden@Ww^T + Wb + Ub)
__device__ float g_scores[SLEN * NB];   // score[s][n] (accumulated via atomics)

// ---------------- helpers ----------------
__device__ __forceinline__ uint32_t smem_u32(const void* p) {
    uint32_t a;
    asm("{ .reg .u64 t; cvta.to.shared.u64 t, %1; cvt.u32.u64 %0, t; }" : "=r"(a) : "l"(p));
    return a;
}
__device__ __forceinline__ uint32_t f2tf32(float x) {
    uint32_t r; asm("cvt.rna.tf32.f32 %0, %1;" : "=r"(r) : "f"(x)); return r;
}
__device__ __forceinline__ float tanh_fast(float x) {
    // tanh(x) = 1 - 2/(e^{2x}+1), e^{2x} = 2^{x * 2/ln2}
    float e, r;
    asm("ex2.approx.f32 %0, %1;" : "=f"(e) : "f"(x * 2.8853900817779268f));
    asm("rcp.approx.f32 %0, %1;" : "=f"(r) : "f"(e + 1.0f));
    return 1.0f - 2.0f * r;
}
#define CP_ASYNC16(dst, src) \
    asm volatile("cp.async.cg.shared.global [%0], [%1], 16;" :: "r"(dst), "l"(src) : "memory")
#define CP_COMMIT()  asm volatile("cp.async.commit_group;" ::: "memory")
#define CP_WAIT(n)   asm volatile("cp.async.wait_group %0;" :: "n"(n) : "memory")

// ============ Kernel 1: whb[k][n] = hidden@Ww^T + Wb + Ub ============
__global__ void __launch_bounds__(512) k_whb(
    const float* __restrict__ hidden, const float* __restrict__ Ww,
    const float* __restrict__ Wb, const float* __restrict__ Ub)
{
    __shared__ float hs[HD];
    const int n = blockIdx.x;
    const int k = threadIdx.x;
    for (int i = threadIdx.x; i < HD; i += 512) hs[i] = hidden[n * HD + i];
    __syncthreads();
    const float4* w4 = (const float4*)(Ww + (size_t)k * HD);
    float acc = 0.f;
#pragma unroll 8
    for (int i = 0; i < HD / 4; ++i) {
        float4 w = w4[i];
        acc += w.x * hs[4*i] + w.y * hs[4*i+1] + w.z * hs[4*i+2] + w.w * hs[4*i+3];
    }
    g_whb[k * NB + n] = acc + Wb[k] + Ub[k];
}

// ============ Kernel 2: tf32 mma.sync GEMM (E@Uw^T) + tanh + v-dot -> scores ============
// CTA tile: 128 sn-rows x 128 kout. grid = (1024, 4).
// 8 warps (4 x 2): warp tile 32(M) x 64(N), m16n8k8 tf32 mma.
// Smem per buffer: A[128][36] + B[128][36] floats (stride 36 => conflict-free frags).
#define TSTRIDE 36
#define BUF_FLOATS (2 * 128 * TSTRIDE)          // A + B, one stage: 9216 floats
#define SMEM_BYTES (2 * BUF_FLOATS * 4)         // 73728 B

__global__ void __launch_bounds__(256) k_gemm_score(
    const float* __restrict__ E, const float* __restrict__ U,
    const float* __restrict__ vw)
{
    extern __shared__ float sm[];
    const int tid = threadIdx.x, lane = tid & 31, wid = tid >> 5;
    const int wm = wid & 3, wn = wid >> 2;
    const int sn0 = blockIdx.x * 128;
    const int cn0 = blockIdx.y * 128;
    const uint32_t sb = smem_u32(sm);

    float acc[2][8][4];
#pragma unroll
    for (int a = 0; a < 2; ++a)
#pragma unroll
        for (int b = 0; b < 8; ++b)
#pragma unroll
            for (int c = 0; c < 4; ++c) acc[a][b][c] = 0.f;

    auto issue = [&](int kt) {
        const float* gA = E + (size_t)sn0 * HD + kt * 32;
        const float* gB = U + (size_t)cn0 * HD + kt * 32;
        const uint32_t base = sb + (uint32_t)(kt & 1) * (BUF_FLOATS * 4);
#pragma unroll
        for (int p = 0; p < 4; ++p) {
            int idx = p * 256 + tid;
            int row = idx >> 3, c4 = idx & 7;
            uint32_t d = base + (uint32_t)(row * TSTRIDE + c4 * 4) * 4;
            CP_ASYNC16(d, gA + (size_t)row * HD + c4 * 4);
            CP_ASYNC16(d + 128 * TSTRIDE * 4, gB + (size_t)row * HD + c4 * 4);
        }
        CP_COMMIT();
    };

    issue(0);
    for (int kt = 0; kt < 16; ++kt) {
        if (kt < 15) { issue(kt + 1); CP_WAIT(1); }
        else         { CP_WAIT(0); }
        __syncthreads();
        const float* As = sm + (kt & 1) * BUF_FLOATS;
        const float* Bs = As + 128 * TSTRIDE;
#pragma unroll
        for (int ks = 0; ks < 4; ++ks) {
            const int k0 = ks * 8;
            uint32_t a[2][4];
#pragma unroll
            for (int mt = 0; mt < 2; ++mt) {
                const float* ap = As + (wm * 32 + mt * 16 + (lane >> 2)) * TSTRIDE + k0 + (lane & 3);
                a[mt][0] = f2tf32(ap[0]);
                a[mt][1] = f2tf32(ap[8 * TSTRIDE]);
                a[mt][2] = f2tf32(ap[4]);
                a[mt][3] = f2tf32(ap[8 * TSTRIDE + 4]);
            }
#pragma unroll
            for (int nt = 0; nt < 8; ++nt) {
                const float* bp = Bs + (wn * 64 + nt * 8 + (lane >> 2)) * TSTRIDE + k0 + (lane & 3);
                uint32_t b0 = f2tf32(bp[0]);
                uint32_t b1 = f2tf32(bp[4]);
#pragma unroll
                for (int mt = 0; mt < 2; ++mt) {
                    asm volatile(
                        "mma.sync.aligned.m16n8k8.row.col.f32.tf32.tf32.f32 "
                        "{%0,%1,%2,%3}, {%4,%5,%6,%7}, {%8,%9}, {%0,%1,%2,%3};"
                        : "+f"(acc[mt][nt][0]), "+f"(acc[mt][nt][1]),
                          "+f"(acc[mt][nt][2]), "+f"(acc[mt][nt][3])
                        : "r"(a[mt][0]), "r"(a[mt][1]), "r"(a[mt][2]), "r"(a[mt][3]),
                          "r"(b0), "r"(b1));
                }
            }
        }
        __syncthreads();
    }

    // ---- fused epilogue: score partial = sum_k v[k] * tanh(whb[k][n] + D) ----
    float* whb_s = sm;            // [128 kout][32 n] — overlay, buffers dead
    float* v_s   = sm + 4096;     // [128]
    for (int i = tid; i < 4096; i += 256) whb_s[i] = g_whb[cn0 * NB + i];
    if (tid < 128) v_s[tid] = vw[cn0 + tid];
    __syncthreads();

#pragma unroll
    for (int mt = 0; mt < 2; ++mt) {
        const int r0 = wm * 32 + mt * 16 + (lane >> 2), r1 = r0 + 8;
        const int nr0 = r0 & 31, nr1 = r1 & 31;
        float s0 = 0.f, s1 = 0.f;
#pragma unroll
        for (int nt = 0; nt < 8; ++nt) {
            const int col = wn * 64 + nt * 8 + (lane & 3) * 2;
#pragma unroll
            for (int e = 0; e < 2; ++e) {
                const float v = v_s[col + e];
                s0 += v * tanh_fast(whb_s[(col + e) * NB + nr0] + acc[mt][nt][e]);
                s1 += v * tanh_fast(whb_s[(col + e) * NB + nr1] + acc[mt][nt][2 + e]);
            }
        }
        s0 += __shfl_xor_sync(~0u, s0, 1); s0 += __shfl_xor_sync(~0u, s0, 2);
        s1 += __shfl_xor_sync(~0u, s1, 1); s1 += __shfl_xor_sync(~0u, s1, 2);
        if ((lane & 3) == 0) {
            atomicAdd(&g_scores[sn0 + r0], s0);
            atomicAdd(&g_scores[sn0 + r1], s1);
        }
    }
}

// ============ Kernel 3: softmax over S per n (v_b cancels: shift-invariant) ============
__global__ void __launch_bounds__(256) k_softmax(float* __restrict__ out_attn)
{
    __shared__ float col[SLEN];
    __shared__ float red[8];
    const int n = blockIdx.x, tid = threadIdx.x;
    float mx = -1e30f;
    for (int i = tid; i < SLEN; i += 256) {
        float v = g_scores[i * NB + n]; col[i] = v; mx = fmaxf(mx, v);
    }
    for (int o = 16; o; o >>= 1) mx = fmaxf(mx, __shfl_xor_sync(~0u, mx, o));
    if ((tid & 31) == 0) red[tid >> 5] = mx;
    __syncthreads();
    mx = red[0];
#pragma unroll
    for (int w = 1; w < 8; ++w) mx = fmaxf(mx, red[w]);
    float sum = 0.f;
    for (int i = tid; i < SLEN; i += 256) {
        float e = __expf(col[i] - mx); col[i] = e; sum += e;
    }
    for (int o = 16; o; o >>= 1) sum += __shfl_xor_sync(~0u, sum, o);
    __syncthreads();
    if ((tid & 31) == 0) red[tid >> 5] = sum;
    __syncthreads();
    sum = 0.f;
#pragma unroll
    for (int w = 0; w < 8; ++w) sum += red[w];
    float inv = 1.f / sum;
    for (int i = tid; i < SLEN; i += 256) out_attn[i * NB + n] = col[i] * inv;
}

// ============ Kernel 4: context[n][h] = sum_s w[s][n] * E[s][n][h] ============
__global__ void __launch_bounds__(128) k_context(
    const float* __restrict__ E, const float* __restrict__ attn,
    float* __restrict__ out_ctx)
{
    __shared__ float ws[512];
    const int hb = blockIdx.x * 128;
    const int s0 = blockIdx.y * 512;
    const int n  = blockIdx.z;
    const int tid = threadIdx.x;
    for (int i = tid; i < 512; i += 128) ws[i] = attn[(s0 + i) * NB + n];
    __syncthreads();
    float a0 = 0.f, a1 = 0.f, a2 = 0.f, a3 = 0.f;
    const float* e = E + ((size_t)(s0 * NB + n)) * HD + hb + tid;
    const size_t step = (size_t)NB * HD;
#pragma unroll 4
    for (int j = 0; j < 512; j += 4) {
        a0 += ws[j]     * e[(size_t)(j)     * step];
        a1 += ws[j + 1] * e[(size_t)(j + 1) * step];
        a2 += ws[j + 2] * e[(size_t)(j + 2) * step];
        a3 += ws[j + 3] * e[(size_t)(j + 3) * step];
    }
    atomicAdd(&out_ctx[n * HD + hb + tid], a0 + a1 + a2 + a3);
}

__global__ void k_zero(float* __restrict__ p) {
    p[blockIdx.x * 256 + threadIdx.x] = 0.f;
}
__global__ void k_zero_scores() {
    g_scores[blockIdx.x * 256 + threadIdx.x] = 0.f;
}

extern "C" void kernel_launch(void* const* d_in, const int* in_sizes, int n_in,
                              void* d_out, int out_size)
{
    (void)in_sizes; (void)n_in; (void)out_size;
    const float* hidden = (const float*)d_in[0];
    const float* E      = (const float*)d_in[1];
    const float* Ww     = (const float*)d_in[2];
    const float* Wb     = (const float*)d_in[3];
    const float* Uw     = (const float*)d_in[4];
    const float* Ub     = (const float*)d_in[5];
    const float* vw     = (const float*)d_in[6];
    float* out = (float*)d_out;

    static int configured = 0;
    if (!configured) {
        cudaFuncSetAttribute(k_gemm_score, cudaFuncAttributeMaxDynamicSharedMemorySize, SMEM_BYTES);
        configured = 1;
    }

    k_whb<<<NB, 512>>>(hidden, Ww, Wb, Ub);
    k_zero_scores<<<(SLEN * NB) / 256, 256>>>();
    dim3 gg(SLEN * NB / 128, 4);
    k_gemm_score<<<gg, 256, SMEM_BYTES>>>(E, Uw, vw);
    k_zero<<<(NB * HD) / 256, 256>>>(out);                 // zero context region
    k_softmax<<<NB, 256>>>(out + NB * HD);                 // attention weights
    dim3 g4(4, 8, NB);
    k_context<<<g4, 128>>>(E, out + NB * HD, out);         // context via atomics
}

// round 5
// speedup vs baseline: 1.3207x; 1.3207x over previous
#include <cuda_runtime.h>
#include <cuda_fp16.h>
#include <cstdint>

#define SLEN 4096
#define NB   32
#define HD   512

// scratch (static device arrays — no allocation)
__device__ __half g_Eh[(size_t)SLEN * NB * HD];   // fp16 copy of encoder_outputs (134MB)
__device__ __half g_Uh[HD * HD];                  // fp16 copy of U_w
__device__ float  g_whb[HD * NB];                 // whb[k][n]: hidden@Ww^T + Wb + Ub
__device__ float  g_scores[SLEN * NB];            // score[s][n] (atomically accumulated)

// ---------------- helpers ----------------
__device__ __forceinline__ uint32_t smem_u32(const void* p) {
    uint32_t a;
    asm("{ .reg .u64 t; cvta.to.shared.u64 t, %1; cvt.u32.u64 %0, t; }" : "=r"(a) : "l"(p));
    return a;
}
__device__ __forceinline__ float tanh_fast(float x) {
    // tanh(x) = 1 - 2/(e^{2x}+1);  e^{2x} = 2^{x * 2/ln2}
    float e, r;
    asm("ex2.approx.f32 %0, %1;" : "=f"(e) : "f"(x * 2.8853900817779268f));
    asm("rcp.approx.f32 %0, %1;" : "=f"(r) : "f"(e + 1.0f));
    return 1.0f - 2.0f * r;
}
#define CP_ASYNC16(dst, src) \
    asm volatile("cp.async.cg.shared.global [%0], [%1], 16;" :: "r"(dst), "l"(src) : "memory")
#define CP_COMMIT()  asm volatile("cp.async.commit_group;" ::: "memory")
#define CP_WAIT(n)   asm volatile("cp.async.wait_group %0;" :: "n"(n) : "memory")

__device__ __forceinline__ void ldsm4(uint32_t& r0, uint32_t& r1, uint32_t& r2, uint32_t& r3, uint32_t a) {
    asm volatile("ldmatrix.sync.aligned.m8n8.x4.shared.b16 {%0,%1,%2,%3}, [%4];"
        : "=r"(r0), "=r"(r1), "=r"(r2), "=r"(r3) : "r"(a));
}
__device__ __forceinline__ void mma_f16(float* c, const uint32_t* a, uint32_t b0, uint32_t b1) {
    asm volatile("mma.sync.aligned.m16n8k16.row.col.f32.f16.f16.f32 "
        "{%0,%1,%2,%3}, {%4,%5,%6,%7}, {%8,%9}, {%0,%1,%2,%3};"
        : "+f"(c[0]), "+f"(c[1]), "+f"(c[2]), "+f"(c[3])
        : "r"(a[0]), "r"(a[1]), "r"(a[2]), "r"(a[3]), "r"(b0), "r"(b1));
}

// ============ Kernel 0: fp32->fp16 convert (E, U) + zero scratch/output ============
__global__ void __launch_bounds__(256) k_convert(
    const float* __restrict__ E, const float* __restrict__ U, float* __restrict__ out_ctx)
{
    const int bid = blockIdx.x, tid = threadIdx.x;
    if (bid < 65536) {                                      // E: 67,108,864 floats
        size_t i = ((size_t)bid * 256 + tid) * 4;
        float4 f = *(const float4*)(E + i);
        __half2 h0 = __floats2half2_rn(f.x, f.y);
        __half2 h1 = __floats2half2_rn(f.z, f.w);
        uint2 u; u.x = *reinterpret_cast<uint32_t*>(&h0); u.y = *reinterpret_cast<uint32_t*>(&h1);
        *(uint2*)(g_Eh + i) = u;
    } else if (bid < 65536 + 256) {                         // U: 262,144 floats
        size_t i = ((size_t)(bid - 65536) * 256 + tid) * 4;
        float4 f = *(const float4*)(U + i);
        __half2 h0 = __floats2half2_rn(f.x, f.y);
        __half2 h1 = __floats2half2_rn(f.z, f.w);
        uint2 u; u.x = *reinterpret_cast<uint32_t*>(&h0); u.y = *reinterpret_cast<uint32_t*>(&h1);
        *(uint2*)(g_Uh + i) = u;
    } else if (bid < 65536 + 256 + 128) {                   // zero g_scores: 131,072 floats
        size_t i = ((size_t)(bid - 65792) * 256 + tid) * 4;
        *(float4*)(g_scores + i) = make_float4(0.f, 0.f, 0.f, 0.f);
    } else {                                                // zero context: 16,384 floats
        size_t i = ((size_t)(bid - 65920) * 256 + tid) * 4;
        *(float4*)(out_ctx + i) = make_float4(0.f, 0.f, 0.f, 0.f);
    }
}

// ============ Kernel 1: whb[k][n] = hidden@Ww^T + Wb + Ub ============
__global__ void __launch_bounds__(512) k_whb(
    const float* __restrict__ hidden, const float* __restrict__ Ww,
    const float* __restrict__ Wb, const float* __restrict__ Ub)
{
    __shared__ float hs[HD];
    const int n = blockIdx.x;
    const int k = threadIdx.x;
    for (int i = threadIdx.x; i < HD; i += 512) hs[i] = hidden[n * HD + i];
    __syncthreads();
    const float4* w4 = (const float4*)(Ww + (size_t)k * HD);
    float acc = 0.f;
#pragma unroll 8
    for (int i = 0; i < HD / 4; ++i) {
        float4 w = w4[i];
        acc += w.x * hs[4*i] + w.y * hs[4*i+1] + w.z * hs[4*i+2] + w.w * hs[4*i+3];
    }
    g_whb[k * NB + n] = acc + Wb[k] + Ub[k];
}

// ============ Kernel 2: fp16 mma GEMM (E@Uw^T) + tanh + v-dot -> scores ============
// CTA tile 256(M) x 128(N), K-stage 64, 3-stage cp.async pipeline.
// 8 warps in 4x2 grid, warp tile 64x64 (mt=4 x m16, nt=8 x n8, k16 mma).
#define BM 256
#define BN 128
#define BK 64
#define ROWB 144                       // 128B data + 16B pad per smem row
#define A_BYTES (BM * ROWB)            // 36864
#define B_BYTES (BN * ROWB)            // 18432
#define STAGE_BYTES (A_BYTES + B_BYTES)
#define NSTAGE 3
#define GSMEM (STAGE_BYTES * NSTAGE)   // 165888
#define NKT (HD / BK)                  // 8

__global__ void __launch_bounds__(256) k_gemm_score(const float* __restrict__ vw)
{
    extern __shared__ char smem[];
    const uint32_t sb = smem_u32(smem);
    const int tid = threadIdx.x, lane = tid & 31, wid = tid >> 5;
    const int wm = wid & 3, wn = wid >> 2;
    const int sn0 = blockIdx.x * BM;
    const int cn0 = blockIdx.y * BN;

    float acc[4][8][4];
#pragma unroll
    for (int a = 0; a < 4; ++a)
#pragma unroll
        for (int b = 0; b < 8; ++b)
#pragma unroll
            for (int c = 0; c < 4; ++c) acc[a][b][c] = 0.f;

    auto issue = [&](int kt) {
        const uint32_t st = sb + (uint32_t)(kt % NSTAGE) * STAGE_BYTES;
#pragma unroll
        for (int i = 0; i < 8; ++i) {              // A: 256 rows x 8 chunks(16B)
            int g = i * 256 + tid;
            int row = g >> 3, c = g & 7;
            CP_ASYNC16(st + (uint32_t)(row * ROWB + c * 16),
                       g_Eh + (size_t)(sn0 + row) * HD + kt * BK + c * 8);
        }
#pragma unroll
        for (int i = 0; i < 4; ++i) {              // B: 128 rows x 8 chunks
            int g = i * 256 + tid;
            int row = g >> 3, c = g & 7;
            CP_ASYNC16(st + A_BYTES + (uint32_t)(row * ROWB + c * 16),
                       g_Uh + (size_t)(cn0 + row) * HD + kt * BK + c * 8);
        }
        CP_COMMIT();
    };

    issue(0); issue(1);

    const int rowA = lane & 15, chA = lane >> 4;              // A ldmatrix lane mapping
    const int rowB = (lane & 7) + ((lane >> 4) << 3), chB = (lane >> 3) & 1;

    for (int kt = 0; kt < NKT; ++kt) {
        if (kt + 1 < NKT) { CP_WAIT(1); } else { CP_WAIT(0); }
        __syncthreads();                 // stage kt ready; all warps done reading stage kt-1
        if (kt + 2 < NKT) issue(kt + 2);
        const uint32_t st = sb + (uint32_t)(kt % NSTAGE) * STAGE_BYTES;
        const uint32_t aB = st + (uint32_t)((wm * 64 + rowA) * ROWB + chA * 16);
        const uint32_t bB = st + A_BYTES + (uint32_t)((wn * 64 + rowB) * ROWB + chB * 16);
#pragma unroll
        for (int ks = 0; ks < 4; ++ks) {
            uint32_t af[4][4];
#pragma unroll
            for (int mt = 0; mt < 4; ++mt)
                ldsm4(af[mt][0], af[mt][1], af[mt][2], af[mt][3],
                      aB + (uint32_t)(mt * 16 * ROWB + ks * 32));
#pragma unroll
            for (int ntp = 0; ntp < 4; ++ntp) {
                uint32_t bf[4];
                ldsm4(bf[0], bf[1], bf[2], bf[3],
                      bB + (uint32_t)(ntp * 16 * ROWB + ks * 32));
#pragma unroll
                for (int mt = 0; mt < 4; ++mt) {
                    mma_f16(acc[mt][2 * ntp],     af[mt], bf[0], bf[1]);
                    mma_f16(acc[mt][2 * ntp + 1], af[mt], bf[2], bf[3]);
                }
            }
        }
    }
    __syncthreads();

    // ---- fused epilogue: score += sum_k v[k] * tanh(whb[k][n] + D) ----
    float* whb_s = (float*)smem;          // [128 col][32 n], stride 33 (conflict-tamed)
    float* v_s   = whb_s + 4224;
    for (int i = tid; i < 4096; i += 256) {
        int col = i >> 5, n = i & 31;
        whb_s[col * 33 + n] = g_whb[cn0 * NB + i];
    }
    if (tid < BN) v_s[tid] = vw[cn0 + tid];
    __syncthreads();

#pragma unroll
    for (int mt = 0; mt < 4; ++mt) {
#pragma unroll
        for (int h = 0; h < 2; ++h) {
            const int m = wm * 64 + mt * 16 + (lane >> 2) + h * 8;
            const int n = m & 31;
            float s = 0.f;
#pragma unroll
            for (int nt = 0; nt < 8; ++nt) {
#pragma unroll
                for (int e = 0; e < 2; ++e) {
                    const int col = wn * 64 + nt * 8 + 2 * (lane & 3) + e;
                    s += v_s[col] * tanh_fast(whb_s[col * 33 + n] + acc[mt][nt][h * 2 + e]);
                }
            }
            s += __shfl_xor_sync(~0u, s, 1);
            s += __shfl_xor_sync(~0u, s, 2);
            if ((lane & 3) == 0) atomicAdd(&g_scores[sn0 + m], s);
        }
    }
}

// ============ Kernel 3: softmax over S per n (v_b cancels: shift-invariant) ============
__global__ void __launch_bounds__(256) k_softmax(float* __restrict__ out_attn)
{
    __shared__ float col[SLEN];
    __shared__ float red[8];
    const int n = blockIdx.x, tid = threadIdx.x;
    float mx = -1e30f;
    for (int i = tid; i < SLEN; i += 256) {
        float v = g_scores[i * NB + n]; col[i] = v; mx = fmaxf(mx, v);
    }
    for (int o = 16; o; o >>= 1) mx = fmaxf(mx, __shfl_xor_sync(~0u, mx, o));
    if ((tid & 31) == 0) red[tid >> 5] = mx;
    __syncthreads();
    mx = red[0];
#pragma unroll
    for (int w = 1; w < 8; ++w) mx = fmaxf(mx, red[w]);
    float sum = 0.f;
    for (int i = tid; i < SLEN; i += 256) {
        float e = __expf(col[i] - mx); col[i] = e; sum += e;
    }
    for (int o = 16; o; o >>= 1) sum += __shfl_xor_sync(~0u, sum, o);
    __syncthreads();
    if ((tid & 31) == 0) red[tid >> 5] = sum;
    __syncthreads();
    sum = 0.f;
#pragma unroll
    for (int w = 0; w < 8; ++w) sum += red[w];
    float inv = 1.f / sum;
    for (int i = tid; i < SLEN; i += 256) out_attn[i * NB + n] = col[i] * inv;
}

// ============ Kernel 4: context[n][h] = sum_s w[s][n] * E[s][n][h] (fp16 E) ============
__global__ void __launch_bounds__(128) k_context(
    const float* __restrict__ attn, float* __restrict__ out_ctx)
{
    __shared__ float ws[512];
    const int hb = blockIdx.x * 256;    // 256 halfs per block (128 thr x half2)
    const int s0 = blockIdx.y * 512;
    const int n  = blockIdx.z;
    const int tid = threadIdx.x;
    for (int i = tid; i < 512; i += 128) ws[i] = attn[(s0 + i) * NB + n];
    __syncthreads();
    const __half2* e2 = (const __half2*)(g_Eh + (size_t)(s0 * NB + n) * HD + hb) + tid;
    const size_t step = (size_t)NB * HD / 2;
    float ax = 0.f, ay = 0.f;
#pragma unroll 4
    for (int j = 0; j < 512; ++j) {
        float2 f = __half22float2(e2[(size_t)j * step]);
        ax += ws[j] * f.x; ay += ws[j] * f.y;
    }
    atomicAdd(&out_ctx[n * HD + hb + tid * 2],     ax);
    atomicAdd(&out_ctx[n * HD + hb + tid * 2 + 1], ay);
}

extern "C" void kernel_launch(void* const* d_in, const int* in_sizes, int n_in,
                              void* d_out, int out_size)
{
    (void)in_sizes; (void)n_in; (void)out_size;
    const float* hidden = (const float*)d_in[0];
    const float* E      = (const float*)d_in[1];
    const float* Ww     = (const float*)d_in[2];
    const float* Wb     = (const float*)d_in[3];
    const float* Uw     = (const float*)d_in[4];
    const float* Ub     = (const float*)d_in[5];
    const float* vw     = (const float*)d_in[6];
    float* out = (float*)d_out;

    cudaFuncSetAttribute(k_gemm_score, cudaFuncAttributeMaxDynamicSharedMemorySize, GSMEM);

    k_convert<<<65936, 256>>>(E, Uw, out);                 // E_h, U_h, zero scores+ctx
    k_whb<<<NB, 512>>>(hidden, Ww, Wb, Ub);
    dim3 gg(SLEN * NB / BM, HD / BN);                      // (512, 4)
    k_gemm_score<<<gg, 256, GSMEM>>>(vw);
    k_softmax<<<NB, 256>>>(out + NB * HD);                 // attention weights
    dim3 g4(2, 8, NB);
    k_context<<<g4, 128>>>(out + NB * HD, out);            // context
}

// round 6
// speedup vs baseline: 1.4626x; 1.1074x over previous
#include <cuda_runtime.h>
#include <cuda_fp16.h>
#include <cstdint>

#define SLEN 4096
#define NB   32
#define HD   512

// scratch (static device arrays — no allocation)
__device__ __half g_Eh[(size_t)SLEN * NB * HD];   // fp16 copy of encoder_outputs (134MB)
__device__ __half g_Uh[HD * HD];                  // fp16 copy of U_w
__device__ float  g_whb[HD * NB];                 // whb[k][n]: hidden@Ww^T + Wb + Ub
__device__ float  g_scores[SLEN * NB];            // score[s][n] (atomically accumulated)

// ---------------- helpers ----------------
__device__ __forceinline__ uint32_t smem_u32(const void* p) {
    uint32_t a;
    asm("{ .reg .u64 t; cvta.to.shared.u64 t, %1; cvt.u32.u64 %0, t; }" : "=r"(a) : "l"(p));
    return a;
}
__device__ __forceinline__ float tanh_fast(float x) {
    // tanh(x) = 1 - 2/(e^{2x}+1);  e^{2x} = 2^{x * 2/ln2}
    float e, r;
    asm("ex2.approx.f32 %0, %1;" : "=f"(e) : "f"(x * 2.8853900817779268f));
    asm("rcp.approx.f32 %0, %1;" : "=f"(r) : "f"(e + 1.0f));
    return 1.0f - 2.0f * r;
}
#define CP_ASYNC16(dst, src) \
    asm volatile("cp.async.cg.shared.global [%0], [%1], 16;" :: "r"(dst), "l"(src) : "memory")
#define CP_COMMIT()  asm volatile("cp.async.commit_group;" ::: "memory")
#define CP_WAIT(n)   asm volatile("cp.async.wait_group %0;" :: "n"(n) : "memory")

__device__ __forceinline__ void ldsm4(uint32_t& r0, uint32_t& r1, uint32_t& r2, uint32_t& r3, uint32_t a) {
    asm volatile("ldmatrix.sync.aligned.m8n8.x4.shared.b16 {%0,%1,%2,%3}, [%4];"
        : "=r"(r0), "=r"(r1), "=r"(r2), "=r"(r3) : "r"(a));
}
__device__ __forceinline__ void mma_f16(float* c, const uint32_t* a, uint32_t b0, uint32_t b1) {
    asm volatile("mma.sync.aligned.m16n8k16.row.col.f32.f16.f16.f32 "
        "{%0,%1,%2,%3}, {%4,%5,%6,%7}, {%8,%9}, {%0,%1,%2,%3};"
        : "+f"(c[0]), "+f"(c[1]), "+f"(c[2]), "+f"(c[3])
        : "r"(a[0]), "r"(a[1]), "r"(a[2]), "r"(a[3]), "r"(b0), "r"(b1));
}

// ============ Kernel 0: fp32->fp16 convert (E, U) + zero scratch + whb ============
// bid zones: [0,65536) E | [65536,65792) U | [65792,65920) zero scores
//            [65920,65936) zero ctx | [65936,65968) whb
__global__ void __launch_bounds__(256) k_convert(
    const float* __restrict__ E, const float* __restrict__ U, float* __restrict__ out_ctx,
    const float* __restrict__ hidden, const float* __restrict__ Ww,
    const float* __restrict__ Wb, const float* __restrict__ Ub)
{
    const int bid = blockIdx.x, tid = threadIdx.x;
    if (bid < 65536) {                                      // E: 67,108,864 floats
        size_t i = ((size_t)bid * 256 + tid) * 4;
        float4 f = *(const float4*)(E + i);
        __half2 h0 = __floats2half2_rn(f.x, f.y);
        __half2 h1 = __floats2half2_rn(f.z, f.w);
        uint2 u; u.x = *reinterpret_cast<uint32_t*>(&h0); u.y = *reinterpret_cast<uint32_t*>(&h1);
        *(uint2*)(g_Eh + i) = u;
    } else if (bid < 65792) {                               // U: 262,144 floats
        size_t i = ((size_t)(bid - 65536) * 256 + tid) * 4;
        float4 f = *(const float4*)(U + i);
        __half2 h0 = __floats2half2_rn(f.x, f.y);
        __half2 h1 = __floats2half2_rn(f.z, f.w);
        uint2 u; u.x = *reinterpret_cast<uint32_t*>(&h0); u.y = *reinterpret_cast<uint32_t*>(&h1);
        *(uint2*)(g_Uh + i) = u;
    } else if (bid < 65920) {                               // zero g_scores
        size_t i = ((size_t)(bid - 65792) * 256 + tid) * 4;
        *(float4*)(g_scores + i) = make_float4(0.f, 0.f, 0.f, 0.f);
    } else if (bid < 65936) {                               // zero context
        size_t i = ((size_t)(bid - 65920) * 256 + tid) * 4;
        *(float4*)(out_ctx + i) = make_float4(0.f, 0.f, 0.f, 0.f);
    } else {                                                // whb for n = bid-65936
        __shared__ float hs[HD];
        const int n = bid - 65936;
        hs[tid] = hidden[n * HD + tid];
        hs[tid + 256] = hidden[n * HD + tid + 256];
        __syncthreads();
#pragma unroll
        for (int kk = 0; kk < 2; ++kk) {
            const int k = kk * 256 + tid;
            const float4* w4 = (const float4*)(Ww + (size_t)k * HD);
            float acc = 0.f;
#pragma unroll 8
            for (int i = 0; i < HD / 4; ++i) {
                float4 w = w4[i];
                acc += w.x * hs[4*i] + w.y * hs[4*i+1] + w.z * hs[4*i+2] + w.w * hs[4*i+3];
            }
            g_whb[k * NB + n] = acc + Wb[k] + Ub[k];
        }
    }
}

// ============ Kernel 1: fp16 mma GEMM (E@Uw^T) + tanh + v-dot -> scores ============
// CTA tile 128(M) x 128(N), K-stage 64, 3-stage cp.async, 2 CTAs/SM.
// 8 warps in 4(m) x 2(n): warp tile 32x64 (mt=2 x m16, nt=8 x n8, k16 mma).
#define BM 128
#define BN 128
#define BK 64
#define ROWB 144                       // 128B data + 16B pad per smem row
#define A_BYTES (BM * ROWB)            // 18432
#define B_BYTES (BN * ROWB)            // 18432
#define STAGE_BYTES (A_BYTES + B_BYTES)
#define NSTAGE 3
#define GSMEM (STAGE_BYTES * NSTAGE)   // 110592
#define NKT (HD / BK)                  // 8

__global__ void __launch_bounds__(256, 2) k_gemm_score(const float* __restrict__ vw)
{
    extern __shared__ char smem[];
    const uint32_t sb = smem_u32(smem);
    const int tid = threadIdx.x, lane = tid & 31, wid = tid >> 5;
    const int wm = wid & 3, wn = wid >> 2;
    const int sn0 = blockIdx.y * BM;      // y = sn-row block (slow)
    const int cn0 = blockIdx.x * BN;      // x = kout column chunk (fast -> E shared in L2)

    float acc[2][8][4];
#pragma unroll
    for (int a = 0; a < 2; ++a)
#pragma unroll
        for (int b = 0; b < 8; ++b)
#pragma unroll
            for (int c = 0; c < 4; ++c) acc[a][b][c] = 0.f;

    auto issue = [&](int kt) {
        const uint32_t st = sb + (uint32_t)(kt % NSTAGE) * STAGE_BYTES;
#pragma unroll
        for (int i = 0; i < 4; ++i) {              // A: 128 rows x 8 chunks(16B)
            int g = i * 256 + tid;
            int row = g >> 3, c = g & 7;
            CP_ASYNC16(st + (uint32_t)(row * ROWB + c * 16),
                       g_Eh + (size_t)(sn0 + row) * HD + kt * BK + c * 8);
        }
#pragma unroll
        for (int i = 0; i < 4; ++i) {              // B: 128 rows x 8 chunks
            int g = i * 256 + tid;
            int row = g >> 3, c = g & 7;
            CP_ASYNC16(st + A_BYTES + (uint32_t)(row * ROWB + c * 16),
                       g_Uh + (size_t)(cn0 + row) * HD + kt * BK + c * 8);
        }
        CP_COMMIT();
    };

    issue(0); issue(1);

    const int rowA = lane & 15, chA = lane >> 4;              // A ldmatrix lane mapping
    const int rowB = (lane & 7) + ((lane >> 4) << 3), chB = (lane >> 3) & 1;

    for (int kt = 0; kt < NKT; ++kt) {
        if (kt + 1 < NKT) { CP_WAIT(1); } else { CP_WAIT(0); }
        __syncthreads();                 // stage kt ready; all warps done with stage kt-1
        if (kt + 2 < NKT) issue(kt + 2);
        const uint32_t st = sb + (uint32_t)(kt % NSTAGE) * STAGE_BYTES;
        const uint32_t aB = st + (uint32_t)((wm * 32 + rowA) * ROWB + chA * 16);
        const uint32_t bB = st + A_BYTES + (uint32_t)((wn * 64 + rowB) * ROWB + chB * 16);
#pragma unroll
        for (int ks = 0; ks < 4; ++ks) {
            uint32_t af[2][4];
#pragma unroll
            for (int mt = 0; mt < 2; ++mt)
                ldsm4(af[mt][0], af[mt][1], af[mt][2], af[mt][3],
                      aB + (uint32_t)(mt * 16 * ROWB + ks * 32));
#pragma unroll
            for (int ntp = 0; ntp < 4; ++ntp) {
                uint32_t bf[4];
                ldsm4(bf[0], bf[1], bf[2], bf[3],
                      bB + (uint32_t)(ntp * 16 * ROWB + ks * 32));
#pragma unroll
                for (int mt = 0; mt < 2; ++mt) {
                    mma_f16(acc[mt][2 * ntp],     af[mt], bf[0], bf[1]);
                    mma_f16(acc[mt][2 * ntp + 1], af[mt], bf[2], bf[3]);
                }
            }
        }
    }
    __syncthreads();

    // ---- fused epilogue: score += sum_k v[k] * tanh(whb[k][n] + D) ----
    float* whb_s = (float*)smem;          // [128 col][32 n], stride 33 (conflict-tamed)
    float* v_s   = whb_s + 4224;
    for (int i = tid; i < 4096; i += 256) {
        int col = i >> 5, n = i & 31;
        whb_s[col * 33 + n] = g_whb[cn0 * NB + i];
    }
    if (tid < BN) v_s[tid] = vw[cn0 + tid];
    __syncthreads();

#pragma unroll
    for (int mt = 0; mt < 2; ++mt) {
#pragma unroll
        for (int h = 0; h < 2; ++h) {
            const int m = wm * 32 + mt * 16 + (lane >> 2) + h * 8;
            const int n = m & 31;
            float s = 0.f;
#pragma unroll
            for (int nt = 0; nt < 8; ++nt) {
#pragma unroll
                for (int e = 0; e < 2; ++e) {
                    const int col = wn * 64 + nt * 8 + 2 * (lane & 3) + e;
                    s += v_s[col] * tanh_fast(whb_s[col * 33 + n] + acc[mt][nt][h * 2 + e]);
                }
            }
            s += __shfl_xor_sync(~0u, s, 1);
            s += __shfl_xor_sync(~0u, s, 2);
            if ((lane & 3) == 0) atomicAdd(&g_scores[sn0 + m], s);
        }
    }
}

// ============ Kernel 2: softmax over S per n (v_b cancels: shift-invariant) ============
__global__ void __launch_bounds__(1024) k_softmax(float* __restrict__ out_attn)
{
    __shared__ float col[SLEN];
    __shared__ float red[32];
    const int n = blockIdx.x, tid = threadIdx.x;
    float mx = -1e30f;
    for (int i = tid; i < SLEN; i += 1024) {
        float v = g_scores[i * NB + n]; col[i] = v; mx = fmaxf(mx, v);
    }
    for (int o = 16; o; o >>= 1) mx = fmaxf(mx, __shfl_xor_sync(~0u, mx, o));
    if ((tid & 31) == 0) red[tid >> 5] = mx;
    __syncthreads();
    mx = red[0];
#pragma unroll
    for (int w = 1; w < 32; ++w) mx = fmaxf(mx, red[w]);
    float sum = 0.f;
    for (int i = tid; i < SLEN; i += 1024) {
        float e = __expf(col[i] - mx); col[i] = e; sum += e;
    }
    for (int o = 16; o; o >>= 1) sum += __shfl_xor_sync(~0u, sum, o);
    __syncthreads();
    if ((tid & 31) == 0) red[tid >> 5] = sum;
    __syncthreads();
    sum = 0.f;
#pragma unroll
    for (int w = 0; w < 32; ++w) sum += red[w];
    float inv = 1.f / sum;
    for (int i = tid; i < SLEN; i += 1024) out_attn[i * NB + n] = col[i] * inv;
}

// ============ Kernel 3: context[n][h] = sum_s w[s][n] * E[s][n][h] (fp16 E) ============
__global__ void __launch_bounds__(128) k_context(
    const float* __restrict__ attn, float* __restrict__ out_ctx)
{
    __shared__ float ws[256];
    const int hb = blockIdx.x * 256;    // 256 halfs per block (128 thr x half2)
    const int s0 = blockIdx.y * 256;    // 16 seq splits
    const int n  = blockIdx.z;
    const int tid = threadIdx.x;
    for (int i = tid; i < 256; i += 128) ws[i] = attn[(s0 + i) * NB + n];
    __syncthreads();
    const __half2* e2 = (const __half2*)(g_Eh + (size_t)(s0 * NB + n) * HD + hb) + tid;
    const size_t step = (size_t)NB * HD / 2;
    float ax = 0.f, ay = 0.f;
#pragma unroll 8
    for (int j = 0; j < 256; ++j) {
        float2 f = __half22float2(e2[(size_t)j * step]);
        ax += ws[j] * f.x; ay += ws[j] * f.y;
    }
    atomicAdd(&out_ctx[n * HD + hb + tid * 2],     ax);
    atomicAdd(&out_ctx[n * HD + hb + tid * 2 + 1], ay);
}

extern "C" void kernel_launch(void* const* d_in, const int* in_sizes, int n_in,
                              void* d_out, int out_size)
{
    (void)in_sizes; (void)n_in; (void)out_size;
    const float* hidden = (const float*)d_in[0];
    const float* E      = (const float*)d_in[1];
    const float* Ww     = (const float*)d_in[2];
    const float* Wb     = (const float*)d_in[3];
    const float* Uw     = (const float*)d_in[4];
    const float* Ub     = (const float*)d_in[5];
    const float* vw     = (const float*)d_in[6];
    float* out = (float*)d_out;

    cudaFuncSetAttribute(k_gemm_score, cudaFuncAttributeMaxDynamicSharedMemorySize, GSMEM);

    k_convert<<<65968, 256>>>(E, Uw, out, hidden, Ww, Wb, Ub);
    dim3 gg(HD / BN, SLEN * NB / BM);                      // (4, 1024): x fast = col chunks
    k_gemm_score<<<gg, 256, GSMEM>>>(vw);
    k_softmax<<<NB, 1024>>>(out + NB * HD);                // attention weights
    dim3 g4(2, 16, NB);
    k_context<<<g4, 128>>>(out + NB * HD, out);            // context
}